// round 11
// baseline (speedup 1.0000x reference)
#include <cuda_runtime.h>
#include <cuda_fp16.h>
#include <cstdint>
#include <cstddef>

#define N_NODES 200000
#define N_EV    100000
#define D_      128
#define PADM    200064          // N rounded up to 128

// ---------------- scratch (device globals; zero-initialized at load) ----------
__device__ unsigned long long g_best[N_NODES];
__device__ int                g_row[N_NODES];
__device__ int                g_count;
__device__ __align__(16) __half g_msg[(size_t)PADM * 512];     // fp16 messages
__device__ __align__(16) __half g_wh[(size_t)384 * 640];       // fp16 weights
__device__ __align__(16) __half g_out[(size_t)PADM * 512];     // [m][r|z|n_i|n_h]

// ---------------- helpers -----------------------------------------------------
__device__ __forceinline__ uint32_t smem_u32(const void* p) {
    uint32_t a;
    asm("{ .reg .u64 t; cvta.to.shared.u64 t, %1; cvt.u32.u64 %0, t; }"
        : "=r"(a) : "l"(p));
    return a;
}
__device__ __forceinline__ void cp16(uint32_t dst, const void* src) {
    asm volatile("cp.async.cg.shared.global [%0], [%1], 16;" :: "r"(dst), "l"(src));
}
// swizzled byte offset of (row r, byte col c) in rows x 128B tile
__device__ __forceinline__ uint32_t swz(int r, int c) {
    return (uint32_t)(r * 128 + ((((c >> 4) ^ (r & 7)) << 4) | (c & 15)));
}
__device__ __forceinline__ void ldsm4(uint32_t* r, uint32_t addr) {
    asm volatile("ldmatrix.sync.aligned.m8n8.x4.shared.b16 {%0,%1,%2,%3}, [%4];"
        : "=r"(r[0]), "=r"(r[1]), "=r"(r[2]), "=r"(r[3]) : "r"(addr));
}
__device__ __forceinline__ void mma16816(float* d, const uint32_t* a, const uint32_t* b) {
    asm volatile("mma.sync.aligned.m16n8k16.row.col.f32.f16.f16.f32 "
        "{%0,%1,%2,%3}, {%4,%5,%6,%7}, {%8,%9}, {%0,%1,%2,%3};"
        : "+f"(d[0]), "+f"(d[1]), "+f"(d[2]), "+f"(d[3])
        : "r"(a[0]), "r"(a[1]), "r"(a[2]), "r"(a[3]), "r"(b[0]), "r"(b[1]));
}

__device__ __forceinline__ float accurate_cosf(float x) {
    const float INV2PI = 0.15915493667125702f;
    const float PI2_HI = 6.28125f;
    const float PI2_LO = 1.9353071795864769e-3f;
    float k = rintf(x * INV2PI);
    float r = fmaf(-k, PI2_HI, x);
    r = fmaf(-k, PI2_LO, r);
    return cosf(r);
}
__device__ __forceinline__ float sigmoidf_(float x) { return 1.0f / (1.0f + expf(-x)); }

// ---------------- K1: merged scatter-argmax + weight prepack ----------------------
// Blocks [0, 192): pack weights (2 rows each). Blocks [192, 192+782): scatter.
#define PREP_PACKW_BLOCKS 192
#define PREP_SCATTER_BLOCKS ((2 * N_EV + 255) / 256)

__global__ void k_prep(const int* __restrict__ src,
                       const int* __restrict__ dst,
                       const float* __restrict__ t,
                       const float* __restrict__ w_ih,
                       const float* __restrict__ w_hh) {
    int b = blockIdx.x;
    if (b < PREP_PACKW_BLOCKS) {
        int n = b * 2 + (threadIdx.x >> 7);
        int tid = threadIdx.x & 127;
        __half* rh = g_wh + (size_t)n * 640;
#pragma unroll
        for (int s = 0; s < 5; s++) {
            int col = s * 128 + tid;
            float w = (s < 4) ? w_ih[(size_t)n * 512 + col]
                              : w_hh[(size_t)n * 128 + tid];
            rh[col] = __float2half_rn(w);
        }
        return;
    }
    int i = (b - PREP_PACKW_BLOCKS) * blockDim.x + threadIdx.x;
    if (i >= 2 * N_EV) return;
    int e = (i < N_EV) ? i : i - N_EV;
    int node = (i < N_EV) ? src[e] : dst[e];
    unsigned long long key =
        (((unsigned long long)__float_as_uint(t[e])) << 32) | (unsigned)(i + 1);
    atomicMax(&g_best[node], key);
}

// ---------------- K3: compact + build fp16 messages (warp per node) --------------
__device__ __forceinline__ uint2 pack4h(float a, float b, float c, float d) {
    __half2 lo = __floats2half2_rn(a, b);
    __half2 hi = __floats2half2_rn(c, d);
    uint2 r;
    r.x = *(uint32_t*)&lo;
    r.y = *(uint32_t*)&hi;
    return r;
}

__global__ void k_build(const int* __restrict__ src,
                        const int* __restrict__ dst,
                        const float* __restrict__ t,
                        const float* __restrict__ memory,
                        const float* __restrict__ last_update,
                        const float* __restrict__ feat,
                        const float* __restrict__ time_w,
                        const float* __restrict__ time_b,
                        float* __restrict__ out_lu) {
    __shared__ int s_flags[8];
    __shared__ int s_base;

    int wid = threadIdx.x >> 5;
    int lane = threadIdx.x & 31;
    int gw = blockIdx.x * 8 + wid;                 // node index
    unsigned long long key = (gw < N_NODES) ? g_best[gw] : 0ULL;
    bool active = (key != 0ULL);

    if (lane == 0) s_flags[wid] = active ? 1 : 0;
    __syncthreads();
    if (threadIdx.x == 0) {
        int total = 0;
#pragma unroll
        for (int w = 0; w < 8; w++) total += s_flags[w];
        s_base = atomicAdd(&g_count, total);
    }
    __syncthreads();
    if (!active) return;
    int row = s_base;
#pragma unroll
    for (int w = 0; w < 8; w++)
        if (w < wid) row += s_flags[w];

    int idx = (int)(key & 0xffffffffu) - 1;
    int e = (idx < N_EV) ? idx : idx - N_EV;
    int other = (idx < N_EV) ? dst[e] : src[e];
    float tt = t[e];
    float dt = tt - last_update[gw];

    int c = lane * 4;
    float4 m0 = *(const float4*)&memory[(size_t)gw * D_ + c];
    float4 m1 = *(const float4*)&memory[(size_t)other * D_ + c];
    float4 tw = *(const float4*)&time_w[c];
    float4 tb = *(const float4*)&time_b[c];
    float4 fv = *(const float4*)&feat[(size_t)e * D_ + c];

    uint2* mrow = (uint2*)(g_msg + (size_t)row * 512);
    mrow[lane]      = pack4h(m0.x, m0.y, m0.z, m0.w);
    mrow[32 + lane] = pack4h(m1.x, m1.y, m1.z, m1.w);
    mrow[64 + lane] = pack4h(accurate_cosf(fmaf(dt, tw.x, tb.x)),
                             accurate_cosf(fmaf(dt, tw.y, tb.y)),
                             accurate_cosf(fmaf(dt, tw.z, tb.z)),
                             accurate_cosf(fmaf(dt, tw.w, tb.w)));
    mrow[96 + lane] = pack4h(fv.x, fv.y, fv.z, fv.w);

    if (lane == 0) {
        g_row[gw] = row;
        if (out_lu) out_lu[gw] = tt;
    }
}

// ---------------- K5: fp16 mma.sync GEMM, balanced 3-region grid (R8 config) ------
#define STAGE 32768
#define NSTEPS 10

__global__ void __launch_bounds__(256, 2)
k_gemm() {
    extern __shared__ char smdyn[];
    const int A = g_count;
    const int mbase = blockIdx.y * 128;
    if (mbase >= A) return;
    const int gy = blockIdx.x;
    const int wrow = gy * 128;

    const int tid = threadIdx.x;
    const int wid = tid >> 5, lane = tid & 31;
    const int m0 = (wid >> 1) * 32, n0 = (wid & 1) * 64;
    const uint32_t smb = smem_u32(smdyn);

    const char* b_mem = (const char*)g_wh + (size_t)wrow * 1280;
    const char* a_mem = (const char*)g_msg;

    auto issue = [&](int s, int buf) {
        int ac = (s < 8) ? s * 128 : (s - 8) * 128;
        int wc = (s < 8) ? s * 128 : 1024 + (s - 8) * 128;
        uint32_t st = smb + buf * STAGE;
#pragma unroll
        for (int i = 0; i < 4; i++) {
            int idx = tid + 256 * i;
            int r = idx >> 3, q = (idx & 7) * 16;
            int gr = mbase + r;
            if (gr >= A) gr = A - 1;
            cp16(st + swz(r, q), a_mem + (size_t)gr * 1024 + ac + q);
        }
#pragma unroll
        for (int i = 0; i < 4; i++) {
            int idx = tid + 256 * i;
            int r = idx >> 3, q = (idx & 7) * 16;
            cp16(st + 16384 + swz(r, q), b_mem + (size_t)r * 1280 + wc + q);
        }
        asm volatile("cp.async.commit_group;" ::: "memory");
    };

    float acc[2][8][4];
#pragma unroll
    for (int mi = 0; mi < 2; mi++)
#pragma unroll
        for (int ni = 0; ni < 8; ni++)
#pragma unroll
            for (int j = 0; j < 4; j++) acc[mi][ni][j] = 0.0f;

    const int g = lane >> 2, t2 = (lane & 3) * 2;
    auto store_acc = [&](int colbase) {
#pragma unroll
        for (int mi = 0; mi < 2; mi++) {
            int row0 = mbase + m0 + mi * 16 + g;
#pragma unroll
            for (int ni = 0; ni < 8; ni++) {
                int col = colbase + n0 + ni * 8 + t2;
                *(__half2*)&g_out[(size_t)row0 * 512 + col] =
                    __floats2half2_rn(acc[mi][ni][0], acc[mi][ni][1]);
                *(__half2*)&g_out[(size_t)(row0 + 8) * 512 + col] =
                    __floats2half2_rn(acc[mi][ni][2], acc[mi][ni][3]);
            }
        }
    };

    issue(0, 0);
    issue(1, 1);

    const int arow = lane & 15;
    const int acoll = (lane >> 4) << 4;
    const int browl = (lane & 7) + ((lane & 16) >> 1);
    const int bcoll = (lane & 8) << 1;

    int buf = 0;
    for (int s = 0; s < NSTEPS; s++) {
        if (s + 1 < NSTEPS)
            asm volatile("cp.async.wait_group 1;" ::: "memory");
        else
            asm volatile("cp.async.wait_group 0;" ::: "memory");
        __syncthreads();
        if (s + 2 < NSTEPS) {
            int nbuf = buf + 2; if (nbuf >= 3) nbuf -= 3;
            issue(s + 2, nbuf);
        }

        if (gy == 2 && s == 8) {
            store_acc(256);
#pragma unroll
            for (int mi = 0; mi < 2; mi++)
#pragma unroll
                for (int ni = 0; ni < 8; ni++)
#pragma unroll
                    for (int j = 0; j < 4; j++) acc[mi][ni][j] = 0.0f;
        }

        uint32_t Ast = smb + buf * STAGE;
        uint32_t Bst = Ast + 16384;

#pragma unroll
        for (int kk = 0; kk < 4; kk++) {
            int kb = kk * 32;
            uint32_t a[2][4];
            ldsm4(a[0], Ast + swz(m0 + arow, kb + acoll));
            ldsm4(a[1], Ast + swz(m0 + 16 + arow, kb + acoll));
#pragma unroll
            for (int np = 0; np < 4; np++) {
                int nb = n0 + np * 16 + browl;
                uint32_t bf[4];
                ldsm4(bf, Bst + swz(nb, kb + bcoll));
#pragma unroll
                for (int mi = 0; mi < 2; mi++) {
                    mma16816(acc[mi][np * 2],     a[mi], bf);
                    mma16816(acc[mi][np * 2 + 1], a[mi], bf + 2);
                }
            }
        }
        if (++buf == 3) buf = 0;
    }

    store_acc((gy == 2) ? 384 : gy * 128);
}

// ---------------- K6: merged GRU epilogue + default copy + state reset -------------
// Biases staged in shared (precombined), read as float4 LDS.
__device__ __forceinline__ void ld8h(const __half* p, float* f) {
    uint4 v = *(const uint4*)p;
    const __half2* h = (const __half2*)&v;
#pragma unroll
    for (int j = 0; j < 4; j++) {
        float2 xy = __half22float2(h[j]);
        f[2 * j] = xy.x; f[2 * j + 1] = xy.y;
    }
}
__device__ __forceinline__ void ld8s(const float* p, float* f) {
    float4 v0 = *(const float4*)p;
    float4 v1 = *(const float4*)(p + 4);
    f[0] = v0.x; f[1] = v0.y; f[2] = v0.z; f[3] = v0.w;
    f[4] = v1.x; f[5] = v1.y; f[6] = v1.z; f[7] = v1.w;
}

__global__ void __launch_bounds__(256)
k_finish(const float* __restrict__ memory,
         const float* __restrict__ last_update,
         const float* __restrict__ b_ih,
         const float* __restrict__ b_hh,
         float* __restrict__ out_mem,
         float* __restrict__ out_lu) {
    __shared__ __align__(16) float s_br[128], s_bz[128], s_bin[128], s_bhn[128];
    {
        int tl = threadIdx.x;
        if (tl < 128) {
            s_br[tl] = b_ih[tl] + b_hh[tl];
            s_bz[tl] = b_ih[128 + tl] + b_hh[128 + tl];
        } else {
            int q = tl - 128;
            s_bin[q] = b_ih[256 + q];
            s_bhn[q] = b_hh[256 + q];
        }
    }
    __syncthreads();

    int i = blockIdx.x * blockDim.x + threadIdx.x;
    if (i == 0) g_count = 0;                 // reset for next invocation
    int node = i >> 4;
    if (node >= N_NODES) return;
    int c = (i & 15) * 8;

    const float* hrow = memory + (size_t)node * D_ + c;
    float* orow = out_mem + (size_t)node * D_ + c;
    float4 h0 = *(const float4*)hrow;
    float4 h1 = *(const float4*)(hrow + 4);

    unsigned long long key = g_best[node];
    if (key == 0ULL) {
        *(float4*)orow = h0;
        *(float4*)(orow + 4) = h1;
        if ((i & 15) == 0 && out_lu) out_lu[node] = last_update[node];
        return;
    }
    if ((i & 15) == 0) g_best[node] = 0ULL;  // self-clean for next invocation
    int m = g_row[node];

    const __half* grow = g_out + (size_t)m * 512;
    float vr[8], vz[8], vni[8], vnh[8];
    ld8h(grow + c, vr);
    ld8h(grow + 128 + c, vz);
    ld8h(grow + 256 + c, vni);
    ld8h(grow + 384 + c, vnh);

    float br[8], bz[8], bin[8], bhn[8];
    ld8s(s_br + c, br);
    ld8s(s_bz + c, bz);
    ld8s(s_bin + c, bin);
    ld8s(s_bhn + c, bhn);

    float hv[8] = {h0.x, h0.y, h0.z, h0.w, h1.x, h1.y, h1.z, h1.w};
    float res[8];
#pragma unroll
    for (int j = 0; j < 8; j++) {
        float r = sigmoidf_(vr[j] + br[j]);
        float z = sigmoidf_(vz[j] + bz[j]);
        float n = tanhf(vni[j] + bin[j] + r * (vnh[j] + bhn[j]));
        res[j] = (1.0f - z) * n + z * hv[j];
    }
    *(float4*)orow = make_float4(res[0], res[1], res[2], res[3]);
    *(float4*)(orow + 4) = make_float4(res[4], res[5], res[6], res[7]);
}

// ---------------- launch -------------------------------------------------------------
extern "C" void kernel_launch(void* const* d_in, const int* in_sizes, int n_in,
                              void* d_out, int out_size) {
    const float* memory      = (const float*)d_in[0];
    const float* last_update = (const float*)d_in[1];
    const float* t           = (const float*)d_in[2];
    const float* feat        = (const float*)d_in[3];
    const float* time_w      = (const float*)d_in[4];
    const float* time_b      = (const float*)d_in[5];
    const float* w_ih        = (const float*)d_in[6];
    const float* w_hh        = (const float*)d_in[7];
    const float* b_ih        = (const float*)d_in[8];
    const float* b_hh        = (const float*)d_in[9];
    const int*   src         = (const int*)d_in[10];
    const int*   dst         = (const int*)d_in[11];

    float* out_mem = (float*)d_out;
    float* out_lu  = (out_size >= N_NODES * D_ + N_NODES)
                         ? out_mem + (size_t)N_NODES * D_ : nullptr;

    cudaFuncSetAttribute(k_gemm, cudaFuncAttributeMaxDynamicSharedMemorySize,
                         3 * STAGE);

    k_prep<<<PREP_PACKW_BLOCKS + PREP_SCATTER_BLOCKS, 256>>>(src, dst, t, w_ih, w_hh);
    k_build<<<(N_NODES + 7) / 8, 256>>>(src, dst, t, memory, last_update,
                                        feat, time_w, time_b, out_lu);
    dim3 grid(3, (N_NODES + 127) / 128);
    k_gemm<<<grid, 256, 3 * STAGE>>>();
    k_finish<<<(N_NODES * 16 + 255) / 256, 256>>>(memory, last_update, b_ih, b_hh,
                                                  out_mem, out_lu);
}

// round 12
// speedup vs baseline: 1.1783x; 1.1783x over previous
#include <cuda_runtime.h>
#include <cuda_fp16.h>
#include <cstdint>
#include <cstddef>

#define N_NODES 200000
#define N_EV    100000
#define D_      128
#define PADM    200064          // N rounded up to 128

// ---------------- scratch (device globals; zero-initialized at load) ----------
__device__ unsigned long long g_best[N_NODES];
__device__ int                g_row[N_NODES];
__device__ int                g_count;
__device__ float              g_bias[512];                     // r|z|n_i|n_h combined
__device__ __align__(16) __half g_msg[(size_t)PADM * 512];     // fp16 messages
__device__ __align__(16) __half g_wh[(size_t)384 * 640];       // fp16 weights
__device__ __align__(16) __half g_out[(size_t)PADM * 512];     // [m][r|z|n_i|n_h] + bias

// ---------------- helpers -----------------------------------------------------
__device__ __forceinline__ uint32_t smem_u32(const void* p) {
    uint32_t a;
    asm("{ .reg .u64 t; cvta.to.shared.u64 t, %1; cvt.u32.u64 %0, t; }"
        : "=r"(a) : "l"(p));
    return a;
}
__device__ __forceinline__ void cp16(uint32_t dst, const void* src) {
    asm volatile("cp.async.cg.shared.global [%0], [%1], 16;" :: "r"(dst), "l"(src));
}
// swizzled byte offset of (row r, byte col c) in rows x 128B tile
__device__ __forceinline__ uint32_t swz(int r, int c) {
    return (uint32_t)(r * 128 + ((((c >> 4) ^ (r & 7)) << 4) | (c & 15)));
}
__device__ __forceinline__ void ldsm4(uint32_t* r, uint32_t addr) {
    asm volatile("ldmatrix.sync.aligned.m8n8.x4.shared.b16 {%0,%1,%2,%3}, [%4];"
        : "=r"(r[0]), "=r"(r[1]), "=r"(r[2]), "=r"(r[3]) : "r"(addr));
}
__device__ __forceinline__ void mma16816(float* d, const uint32_t* a, const uint32_t* b) {
    asm volatile("mma.sync.aligned.m16n8k16.row.col.f32.f16.f16.f32 "
        "{%0,%1,%2,%3}, {%4,%5,%6,%7}, {%8,%9}, {%0,%1,%2,%3};"
        : "+f"(d[0]), "+f"(d[1]), "+f"(d[2]), "+f"(d[3])
        : "r"(a[0]), "r"(a[1]), "r"(a[2]), "r"(a[3]), "r"(b[0]), "r"(b[1]));
}

__device__ __forceinline__ float accurate_cosf(float x) {
    const float INV2PI = 0.15915493667125702f;
    const float PI2_HI = 6.28125f;
    const float PI2_LO = 1.9353071795864769e-3f;
    float k = rintf(x * INV2PI);
    float r = fmaf(-k, PI2_HI, x);
    r = fmaf(-k, PI2_LO, r);
    return cosf(r);
}
__device__ __forceinline__ float sigmoidf_(float x) { return 1.0f / (1.0f + expf(-x)); }

// ---------------- K1: merged scatter + weight prepack + bias precombine ----------
// Blocks [0,192): pack weights (2 rows each). Block 192: biases. Rest: scatter.
#define PREP_PACKW_BLOCKS 192
#define PREP_SCATTER_BLOCKS ((2 * N_EV + 255) / 256)

__global__ void k_prep(const int* __restrict__ src,
                       const int* __restrict__ dst,
                       const float* __restrict__ t,
                       const float* __restrict__ w_ih,
                       const float* __restrict__ w_hh,
                       const float* __restrict__ b_ih,
                       const float* __restrict__ b_hh) {
    int b = blockIdx.x;
    if (b < PREP_PACKW_BLOCKS) {
        int n = b * 2 + (threadIdx.x >> 7);
        int tid = threadIdx.x & 127;
        __half* rh = g_wh + (size_t)n * 640;
#pragma unroll
        for (int s = 0; s < 5; s++) {
            int col = s * 128 + tid;
            float w = (s < 4) ? w_ih[(size_t)n * 512 + col]
                              : w_hh[(size_t)n * 128 + tid];
            rh[col] = __float2half_rn(w);
        }
        return;
    }
    if (b == PREP_PACKW_BLOCKS) {
        int tl = threadIdx.x;
        // [0:256) = r|z combined sums
        g_bias[tl] = b_ih[tl] + b_hh[tl];
        // [256:384) = b_ih n-gate, [384:512) = b_hh n-gate
        if (tl < 128) g_bias[256 + tl] = b_ih[256 + tl];
        else          g_bias[384 + (tl - 128)] = b_hh[256 + (tl - 128)];
        return;
    }
    int i = (b - PREP_PACKW_BLOCKS - 1) * blockDim.x + threadIdx.x;
    if (i >= 2 * N_EV) return;
    int e = (i < N_EV) ? i : i - N_EV;
    int node = (i < N_EV) ? src[e] : dst[e];
    unsigned long long key =
        (((unsigned long long)__float_as_uint(t[e])) << 32) | (unsigned)(i + 1);
    atomicMax(&g_best[node], key);
}

// ---------------- K3: compact + build fp16 messages (warp per node) --------------
__device__ __forceinline__ uint2 pack4h(float a, float b, float c, float d) {
    __half2 lo = __floats2half2_rn(a, b);
    __half2 hi = __floats2half2_rn(c, d);
    uint2 r;
    r.x = *(uint32_t*)&lo;
    r.y = *(uint32_t*)&hi;
    return r;
}

__global__ void k_build(const int* __restrict__ src,
                        const int* __restrict__ dst,
                        const float* __restrict__ t,
                        const float* __restrict__ memory,
                        const float* __restrict__ last_update,
                        const float* __restrict__ feat,
                        const float* __restrict__ time_w,
                        const float* __restrict__ time_b,
                        float* __restrict__ out_lu) {
    __shared__ int s_flags[8];
    __shared__ int s_base;

    int wid = threadIdx.x >> 5;
    int lane = threadIdx.x & 31;
    int gw = blockIdx.x * 8 + wid;                 // node index
    unsigned long long key = (gw < N_NODES) ? g_best[gw] : 0ULL;
    bool active = (key != 0ULL);

    if (lane == 0) s_flags[wid] = active ? 1 : 0;
    __syncthreads();
    if (threadIdx.x == 0) {
        int total = 0;
#pragma unroll
        for (int w = 0; w < 8; w++) total += s_flags[w];
        s_base = atomicAdd(&g_count, total);
    }
    __syncthreads();
    if (!active) return;
    int row = s_base;
#pragma unroll
    for (int w = 0; w < 8; w++)
        if (w < wid) row += s_flags[w];

    int idx = (int)(key & 0xffffffffu) - 1;
    int e = (idx < N_EV) ? idx : idx - N_EV;
    int other = (idx < N_EV) ? dst[e] : src[e];
    float tt = t[e];
    float dt = tt - last_update[gw];

    int c = lane * 4;
    float4 m0 = *(const float4*)&memory[(size_t)gw * D_ + c];
    float4 m1 = *(const float4*)&memory[(size_t)other * D_ + c];
    float4 tw = *(const float4*)&time_w[c];
    float4 tb = *(const float4*)&time_b[c];
    float4 fv = *(const float4*)&feat[(size_t)e * D_ + c];

    uint2* mrow = (uint2*)(g_msg + (size_t)row * 512);
    mrow[lane]      = pack4h(m0.x, m0.y, m0.z, m0.w);
    mrow[32 + lane] = pack4h(m1.x, m1.y, m1.z, m1.w);
    mrow[64 + lane] = pack4h(accurate_cosf(fmaf(dt, tw.x, tb.x)),
                             accurate_cosf(fmaf(dt, tw.y, tb.y)),
                             accurate_cosf(fmaf(dt, tw.z, tb.z)),
                             accurate_cosf(fmaf(dt, tw.w, tb.w)));
    mrow[96 + lane] = pack4h(fv.x, fv.y, fv.z, fv.w);

    if (lane == 0) {
        g_row[gw] = row;
        if (out_lu) out_lu[gw] = tt;
    }
}

// ---------------- K5: fp16 mma.sync GEMM + bias in epilogue -----------------------
#define STAGE 32768
#define NSTEPS 10

__global__ void __launch_bounds__(256, 2)
k_gemm() {
    extern __shared__ char smdyn[];
    const int A = g_count;
    const int mbase = blockIdx.y * 128;
    if (mbase >= A) return;
    const int gy = blockIdx.x;
    const int wrow = gy * 128;

    const int tid = threadIdx.x;
    const int wid = tid >> 5, lane = tid & 31;
    const int m0 = (wid >> 1) * 32, n0 = (wid & 1) * 64;
    const uint32_t smb = smem_u32(smdyn);

    const char* b_mem = (const char*)g_wh + (size_t)wrow * 1280;
    const char* a_mem = (const char*)g_msg;

    auto issue = [&](int s, int buf) {
        int ac = (s < 8) ? s * 128 : (s - 8) * 128;
        int wc = (s < 8) ? s * 128 : 1024 + (s - 8) * 128;
        uint32_t st = smb + buf * STAGE;
#pragma unroll
        for (int i = 0; i < 4; i++) {
            int idx = tid + 256 * i;
            int r = idx >> 3, q = (idx & 7) * 16;
            int gr = mbase + r;
            if (gr >= A) gr = A - 1;
            cp16(st + swz(r, q), a_mem + (size_t)gr * 1024 + ac + q);
        }
#pragma unroll
        for (int i = 0; i < 4; i++) {
            int idx = tid + 256 * i;
            int r = idx >> 3, q = (idx & 7) * 16;
            cp16(st + 16384 + swz(r, q), b_mem + (size_t)r * 1280 + wc + q);
        }
        asm volatile("cp.async.commit_group;" ::: "memory");
    };

    float acc[2][8][4];
#pragma unroll
    for (int mi = 0; mi < 2; mi++)
#pragma unroll
        for (int ni = 0; ni < 8; ni++)
#pragma unroll
            for (int j = 0; j < 4; j++) acc[mi][ni][j] = 0.0f;

    const int g = lane >> 2, t2 = (lane & 3) * 2;
    auto store_acc = [&](int colbase) {
#pragma unroll
        for (int mi = 0; mi < 2; mi++) {
            int row0 = mbase + m0 + mi * 16 + g;
#pragma unroll
            for (int ni = 0; ni < 8; ni++) {
                int col = colbase + n0 + ni * 8 + t2;
                float2 bv = *(const float2*)&g_bias[col];
                *(__half2*)&g_out[(size_t)row0 * 512 + col] =
                    __floats2half2_rn(acc[mi][ni][0] + bv.x, acc[mi][ni][1] + bv.y);
                *(__half2*)&g_out[(size_t)(row0 + 8) * 512 + col] =
                    __floats2half2_rn(acc[mi][ni][2] + bv.x, acc[mi][ni][3] + bv.y);
            }
        }
    };

    issue(0, 0);
    issue(1, 1);

    const int arow = lane & 15;
    const int acoll = (lane >> 4) << 4;
    const int browl = (lane & 7) + ((lane & 16) >> 1);
    const int bcoll = (lane & 8) << 1;

    int buf = 0;
    for (int s = 0; s < NSTEPS; s++) {
        if (s + 1 < NSTEPS)
            asm volatile("cp.async.wait_group 1;" ::: "memory");
        else
            asm volatile("cp.async.wait_group 0;" ::: "memory");
        __syncthreads();
        if (s + 2 < NSTEPS) {
            int nbuf = buf + 2; if (nbuf >= 3) nbuf -= 3;
            issue(s + 2, nbuf);
        }

        if (gy == 2 && s == 8) {
            store_acc(256);
#pragma unroll
            for (int mi = 0; mi < 2; mi++)
#pragma unroll
                for (int ni = 0; ni < 8; ni++)
#pragma unroll
                    for (int j = 0; j < 4; j++) acc[mi][ni][j] = 0.0f;
        }

        uint32_t Ast = smb + buf * STAGE;
        uint32_t Bst = Ast + 16384;

#pragma unroll
        for (int kk = 0; kk < 4; kk++) {
            int kb = kk * 32;
            uint32_t a[2][4];
            ldsm4(a[0], Ast + swz(m0 + arow, kb + acoll));
            ldsm4(a[1], Ast + swz(m0 + 16 + arow, kb + acoll));
#pragma unroll
            for (int np = 0; np < 4; np++) {
                int nb = n0 + np * 16 + browl;
                uint32_t bf[4];
                ldsm4(bf, Bst + swz(nb, kb + bcoll));
#pragma unroll
                for (int mi = 0; mi < 2; mi++) {
                    mma16816(acc[mi][np * 2],     a[mi], bf);
                    mma16816(acc[mi][np * 2 + 1], a[mi], bf + 2);
                }
            }
        }
        if (++buf == 3) buf = 0;
    }

    store_acc((gy == 2) ? 384 : gy * 128);
}

// ---------------- K6: merged GRU epilogue + default copy + state reset -------------
// Preacts in g_out already include biases: pure elementwise math, no bias loads.
__device__ __forceinline__ void ld8h(const __half* p, float* f) {
    uint4 v = *(const uint4*)p;
    const __half2* h = (const __half2*)&v;
#pragma unroll
    for (int j = 0; j < 4; j++) {
        float2 xy = __half22float2(h[j]);
        f[2 * j] = xy.x; f[2 * j + 1] = xy.y;
    }
}

__global__ void k_finish(const float* __restrict__ memory,
                         const float* __restrict__ last_update,
                         float* __restrict__ out_mem,
                         float* __restrict__ out_lu) {
    int i = blockIdx.x * blockDim.x + threadIdx.x;
    if (i == 0) g_count = 0;                 // reset for next invocation
    int node = i >> 4;
    if (node >= N_NODES) return;
    int c = (i & 15) * 8;

    const float* hrow = memory + (size_t)node * D_ + c;
    float* orow = out_mem + (size_t)node * D_ + c;
    float4 h0 = *(const float4*)hrow;
    float4 h1 = *(const float4*)(hrow + 4);

    unsigned long long key = g_best[node];
    if (key == 0ULL) {
        *(float4*)orow = h0;
        *(float4*)(orow + 4) = h1;
        if ((i & 15) == 0 && out_lu) out_lu[node] = last_update[node];
        return;
    }
    if ((i & 15) == 0) g_best[node] = 0ULL;  // self-clean for next invocation
    int m = g_row[node];

    const __half* grow = g_out + (size_t)m * 512;
    float vr[8], vz[8], vni[8], vnh[8];
    ld8h(grow + c, vr);
    ld8h(grow + 128 + c, vz);
    ld8h(grow + 256 + c, vni);
    ld8h(grow + 384 + c, vnh);

    float hv[8] = {h0.x, h0.y, h0.z, h0.w, h1.x, h1.y, h1.z, h1.w};
    float res[8];
#pragma unroll
    for (int j = 0; j < 8; j++) {
        float r = sigmoidf_(vr[j]);
        float z = sigmoidf_(vz[j]);
        float n = tanhf(vni[j] + r * vnh[j]);
        res[j] = (1.0f - z) * n + z * hv[j];
    }
    *(float4*)orow = make_float4(res[0], res[1], res[2], res[3]);
    *(float4*)(orow + 4) = make_float4(res[4], res[5], res[6], res[7]);
}

// ---------------- launch -------------------------------------------------------------
extern "C" void kernel_launch(void* const* d_in, const int* in_sizes, int n_in,
                              void* d_out, int out_size) {
    const float* memory      = (const float*)d_in[0];
    const float* last_update = (const float*)d_in[1];
    const float* t           = (const float*)d_in[2];
    const float* feat        = (const float*)d_in[3];
    const float* time_w      = (const float*)d_in[4];
    const float* time_b      = (const float*)d_in[5];
    const float* w_ih        = (const float*)d_in[6];
    const float* w_hh        = (const float*)d_in[7];
    const float* b_ih        = (const float*)d_in[8];
    const float* b_hh        = (const float*)d_in[9];
    const int*   src         = (const int*)d_in[10];
    const int*   dst         = (const int*)d_in[11];

    float* out_mem = (float*)d_out;
    float* out_lu  = (out_size >= N_NODES * D_ + N_NODES)
                         ? out_mem + (size_t)N_NODES * D_ : nullptr;

    cudaFuncSetAttribute(k_gemm, cudaFuncAttributeMaxDynamicSharedMemorySize,
                         3 * STAGE);

    k_prep<<<PREP_PACKW_BLOCKS + 1 + PREP_SCATTER_BLOCKS, 256>>>(
        src, dst, t, w_ih, w_hh, b_ih, b_hh);
    k_build<<<(N_NODES + 7) / 8, 256>>>(src, dst, t, memory, last_update,
                                        feat, time_w, time_b, out_lu);
    dim3 grid(3, (N_NODES + 127) / 128);
    k_gemm<<<grid, 256, 3 * STAGE>>>();
    k_finish<<<(N_NODES * 16 + 255) / 256, 256>>>(memory, last_update,
                                                  out_mem, out_lu);
}